// round 6
// baseline (speedup 1.0000x reference)
#include <cuda_runtime.h>

#define BATCH  16384
#define NNZ    819200
#define KDIM   16
#define VOCAB  1000000
#define CHUNK  128
#define NWARPS (NNZ / CHUNK)   // 6400, exact

__device__ int   g_row_ptr[BATCH + 1];
__device__ int   g_is64;
__device__ float g_t1[BATCH * KDIM];   // boundary-row scratch
__device__ float g_c [BATCH];          // boundary-row scratch: first - 0.5*t2

// ---------------------------------------------------------------------------
// dtype detection: words 2i+1 (i < NNZ/2) are in-bounds under both views.
// int64 view -> high words all 0; int32 view -> sorted index vals ~8191 != 0.
// ---------------------------------------------------------------------------
__device__ __forceinline__ int detect_is64(const unsigned int* __restrict__ w) {
    unsigned int acc = 0;
    int base = NNZ / 2 - 8;
#pragma unroll
    for (int i = 0; i < 8; i++) acc |= w[2 * (base + i) + 1];
    return (acc == 0u) ? 1 : 0;
}

template <bool IS64>
__device__ __forceinline__ int load_idx(const void* __restrict__ p, int i) {
    if (IS64) return (int)__ldg((const long long*)p + i);
    return __ldg((const int*)p + i);
}

__device__ __forceinline__ float warp_sum(float r) {
#pragma unroll
    for (int o = 16; o > 0; o >>= 1)
        r += __shfl_xor_sync(0xffffffffu, r, o);
    return r;
}

// ---------------------------------------------------------------------------
// K1: rowptr via adjacent difference + scratch zeroing (same launch).
// ---------------------------------------------------------------------------
__global__ void __launch_bounds__(256)
rowptr_kernel(const void* __restrict__ index) {
    __shared__ int s_is64;
    if (threadIdx.x == 0) {
        int is64 = detect_is64((const unsigned int*)index);
        s_is64 = is64;
        if (blockIdx.x == 0) g_is64 = is64;
    }
    __syncthreads();
    const int is64 = s_is64;

    const int i = blockIdx.x * blockDim.x + threadIdx.x;
    if (i < BATCH * KDIM) g_t1[i] = 0.f;
    if (i < BATCH)        g_c[i]  = 0.f;
    if (i >= NNZ) return;

    int a, b;
    if (is64) {
        a = load_idx<true>(index, i);
        b = (i + 1 < NNZ) ? load_idx<true>(index, i + 1) : BATCH;
    } else {
        a = load_idx<false>(index, i);
        b = (i + 1 < NNZ) ? load_idx<false>(index, i + 1) : BATCH;
    }
    if (i == 0)
        for (int r = 0; r <= a; r++) g_row_ptr[r] = 0;
    for (int r = a + 1; r <= b; r++) g_row_ptr[r] = i + 1;
}

// ---------------------------------------------------------------------------
// K2: uniform chunks. Warp owns nnz [w*128, (w+1)*128). Walks rows inside.
// Interior rows -> direct out[] write. Straddling rows -> atomic partials.
// Accumulators per lane: t1 float4 (k = 4m..4m+3, octet g) and c = first-0.5*t2.
// ---------------------------------------------------------------------------
template <bool IS64>
__device__ __forceinline__ void fm_chunk(
        int ws, int we, int lane,
        const void* __restrict__ index,
        const void* __restrict__ feats,
        const float* __restrict__ values,
        const float* __restrict__ weights,
        const float* __restrict__ embedding,
        float bias_v, float* __restrict__ out) {
    const int g = lane >> 2;
    const int m = lane & 3;

    int  j = ws;
    int  r = load_idx<IS64>(index, ws);
    bool start_interior = (ws == 0) || (load_idx<IS64>(index, ws - 1) != r);

    while (j < we) {
        const int re_full = g_row_ptr[r + 1];
        const int seg_e   = (re_full < we) ? re_full : we;

        float4 t1 = make_float4(0.f, 0.f, 0.f, 0.f);
        float  c  = 0.f;

        for (int base = j; base < seg_e; base += 32) {
            const int jj = base + lane;
            const int cl = (jj < seg_e) ? jj : (seg_e - 1);
            const int   f = load_idx<IS64>(feats, cl);
            const float v = (jj < seg_e) ? __ldg(values + jj) : 0.f;
            c += __ldg(weights + f) * v;
            const int fr = f * KDIM;
#pragma unroll
            for (int t = 0; t < 4; t++) {
                const int   src = 8 * t + g;
                const int   frb = __shfl_sync(0xffffffffu, fr, src);
                const float vb  = __shfl_sync(0xffffffffu, v,  src);
                const float4 e4 = __ldg((const float4*)(embedding + frb) + m);
                const float e0 = e4.x * vb, e1 = e4.y * vb,
                            e2 = e4.z * vb, e3 = e4.w * vb;
                t1.x += e0; t1.y += e1; t1.z += e2; t1.w += e3;
                c -= 0.5f * (e0 * e0 + e1 * e1 + e2 * e2 + e3 * e3);
            }
        }

        // reduce t1 over the 8 octet-groups (lane bits 2..4)
#pragma unroll
        for (int o = 4; o <= 16; o <<= 1) {
            t1.x += __shfl_xor_sync(0xffffffffu, t1.x, o);
            t1.y += __shfl_xor_sync(0xffffffffu, t1.y, o);
            t1.z += __shfl_xor_sync(0xffffffffu, t1.z, o);
            t1.w += __shfl_xor_sync(0xffffffffu, t1.w, o);
        }

        const bool interior = (re_full <= we) && start_interior;
        if (interior) {
            // |t1|^2 replicated 8x across groups -> 0.5/8 = 0.0625
            float rr = 0.0625f * (t1.x * t1.x + t1.y * t1.y +
                                  t1.z * t1.z + t1.w * t1.w) + c;
            rr = warp_sum(rr);
            if (lane == 0)
                out[r] = 1.0f / (1.0f + expf(-(rr + bias_v)));
        } else {
            const float ctot = warp_sum(c);
            if (lane == 0) atomicAdd(g_c + r, ctot);
            if (lane < 4) {           // g==0 lanes hold the reduced float4s
                float* p = g_t1 + r * KDIM + 4 * lane;
                atomicAdd(p + 0, t1.x);
                atomicAdd(p + 1, t1.y);
                atomicAdd(p + 2, t1.z);
                atomicAdd(p + 3, t1.w);
            }
        }

        j = seg_e;
        if (j < we) r = load_idx<IS64>(index, j);
        start_interior = true;   // later segments start inside the chunk
    }
}

__global__ void __launch_bounds__(256)
fm_main(const void* __restrict__ index,
        const void* __restrict__ feats,
        const float* __restrict__ values,
        const float* __restrict__ weights,
        const float* __restrict__ embedding,
        const float* __restrict__ bias,
        float* __restrict__ out) {
    const int warp = (blockIdx.x * blockDim.x + threadIdx.x) >> 5;
    const int lane = threadIdx.x & 31;
    if (warp >= NWARPS) return;

    const float bias_v = __ldg(bias);
    const int ws = warp * CHUNK;
    const int we = ws + CHUNK;

    if (g_is64) fm_chunk<true >(ws, we, lane, index, feats, values, weights, embedding, bias_v, out);
    else        fm_chunk<false>(ws, we, lane, index, feats, values, weights, embedding, bias_v, out);
}

// ---------------------------------------------------------------------------
// K3: finish non-interior rows (straddlers + empty rows).
// ---------------------------------------------------------------------------
__global__ void __launch_bounds__(256)
finish_kernel(const float* __restrict__ bias, float* __restrict__ out) {
    const int r = blockIdx.x * blockDim.x + threadIdx.x;
    if (r >= BATCH) return;
    const int rs = g_row_ptr[r];
    const int re = g_row_ptr[r + 1];
    const bool interior = (re > rs) && ((rs / CHUNK) == ((re - 1) / CHUNK));
    if (interior) return;

    float acc = g_c[r];
    const float4* p = (const float4*)(g_t1 + r * KDIM);
#pragma unroll
    for (int i = 0; i < 4; i++) {
        const float4 a = p[i];
        acc += 0.5f * (a.x * a.x + a.y * a.y + a.z * a.z + a.w * a.w);
    }
    out[r] = 1.0f / (1.0f + expf(-(acc + __ldg(bias))));
}

// ---------------------------------------------------------------------------
extern "C" void kernel_launch(void* const* d_in, const int* in_sizes, int n_in,
                              void* d_out, int out_size) {
    const void*  index_p   = nullptr;
    const void*  feats_p   = nullptr;
    const float* values_p  = nullptr;
    const float* bias_p    = nullptr;
    const float* weights_p = nullptr;
    const float* embed_p   = nullptr;

    int triple = 0;
    for (int i = 0; i < n_in; i++) {
        int sz = in_sizes[i];
        if (sz == NNZ) {
            if      (triple == 0) index_p  = d_in[i];
            else if (triple == 1) feats_p  = d_in[i];
            else                  values_p = (const float*)d_in[i];
            triple++;
        } else if (sz == VOCAB) {
            weights_p = (const float*)d_in[i];
        } else if (sz == VOCAB * KDIM) {
            embed_p = (const float*)d_in[i];
        } else if (sz == 1) {
            bias_p = (const float*)d_in[i];   // last size-1 input is bias
        }
    }

    float* out = (float*)d_out;
    (void)out_size;

    rowptr_kernel<<<(NNZ + 255) / 256, 256>>>(index_p);
    fm_main<<<(NWARPS * 32 + 255) / 256, 256>>>(index_p, feats_p, values_p,
                                                weights_p, embed_p, bias_p, out);
    finish_kernel<<<(BATCH + 255) / 256, 256>>>(bias_p, out);
}

// round 7
// speedup vs baseline: 1.7130x; 1.7130x over previous
#include <cuda_runtime.h>

#define BATCH  16384
#define NNZ    819200
#define KDIM   16
#define VOCAB  1000000
#define CAP    64          // rows per super-chunk (covers ~98% of rows whole)

__device__ int g_row_ptr[BATCH + 1];
__device__ int g_is64;

// ---------------------------------------------------------------------------
// dtype detection: words 2i+1 (i < NNZ/2) are in-bounds under both views.
// int64 view -> high words all 0; int32 view -> sorted index vals ~8191 != 0.
// ---------------------------------------------------------------------------
__device__ __forceinline__ int detect_is64(const unsigned int* __restrict__ w) {
    unsigned int acc = 0;
    int base = NNZ / 2 - 8;
#pragma unroll
    for (int i = 0; i < 8; i++) acc |= w[2 * (base + i) + 1];
    return (acc == 0u) ? 1 : 0;
}

template <bool IS64>
__device__ __forceinline__ int load_idx(const void* __restrict__ p, int i) {
    if (IS64) return (int)__ldg((const long long*)p + i);
    return __ldg((const int*)p + i);
}

__device__ __forceinline__ float warp_sum(float r) {
#pragma unroll
    for (int o = 16; o > 0; o >>= 1)
        r += __shfl_xor_sync(0xffffffffu, r, o);
    return r;
}

__device__ __forceinline__ unsigned int smem_u32(const void* p) {
    return (unsigned int)__cvta_generic_to_shared(p);
}
__device__ __forceinline__ void cp16(unsigned int dst, const void* src) {
    asm volatile("cp.async.cg.shared.global [%0], [%1], 16;" :: "r"(dst), "l"(src));
}
__device__ __forceinline__ void cp4(unsigned int dst, const void* src) {
    asm volatile("cp.async.ca.shared.global [%0], [%1], 4;" :: "r"(dst), "l"(src));
}
__device__ __forceinline__ void cp_commit() {
    asm volatile("cp.async.commit_group;");
}
__device__ __forceinline__ void cp_wait0() {
    asm volatile("cp.async.wait_group 0;");
}

// ---------------------------------------------------------------------------
// K1: rowptr via adjacent difference over the sorted index (R5 version).
// ---------------------------------------------------------------------------
__global__ void __launch_bounds__(256)
rowptr_kernel(const void* __restrict__ index) {
    __shared__ int s_is64;
    if (threadIdx.x == 0) {
        int is64 = detect_is64((const unsigned int*)index);
        s_is64 = is64;
        if (blockIdx.x == 0) g_is64 = is64;
    }
    __syncthreads();
    const int is64 = s_is64;

    const int i = blockIdx.x * blockDim.x + threadIdx.x;
    if (i >= NNZ) return;

    int a, b;
    if (is64) {
        a = load_idx<true>(index, i);
        b = (i + 1 < NNZ) ? load_idx<true>(index, i + 1) : BATCH;
    } else {
        a = load_idx<false>(index, i);
        b = (i + 1 < NNZ) ? load_idx<false>(index, i + 1) : BATCH;
    }
    if (i == 0)
        for (int r = 0; r <= a; r++) g_row_ptr[r] = 0;
    for (int r = a + 1; r <= b; r++) g_row_ptr[r] = i + 1;
}

// ---------------------------------------------------------------------------
// K2: warp per row; entire row's gather traffic staged to smem via cp.async
// (register-free in-flight loads), then consumed with conflict-free LDS.128.
// ---------------------------------------------------------------------------
struct __align__(16) WarpBuf {
    float4 emb[CAP * 4];   // row r pieces at emb[4r .. 4r+3]   (4096 B)
    float  w[CAP];         // weights[feats[row]]                (256 B)
    float  v[CAP];         // values[row]                        (256 B)
};

template <bool IS64>
__device__ __forceinline__ float fm_row(
        int s, int e, int lane, WarpBuf* buf,
        const void* __restrict__ feats,
        const float* __restrict__ values,
        const float* __restrict__ weights,
        const float* __restrict__ embedding) {
    const int g = lane >> 2;   // row-slot within an octet
    const int m = lane & 3;    // float4 slot: k = 4m .. 4m+3

    float4 t1 = make_float4(0.f, 0.f, 0.f, 0.f);
    float  t2 = 0.f, first = 0.f;

    const unsigned int emb_s = smem_u32(buf->emb);
    const unsigned int w_s   = smem_u32(buf->w);
    const unsigned int v_s   = smem_u32(buf->v);

    for (int base = s; base < e; base += CAP) {
        const int n = min(e - base, CAP);

        // ---- fill: embedding pieces (4 x 16B per row), all in flight ----
        for (int p = lane; p < 4 * n; p += 32) {
            const int row = p >> 2, q = p & 3;
            const int f = load_idx<IS64>(feats, base + row);  // 4-lane bcast
            cp16(emb_s + (unsigned)p * 16u,
                 embedding + (size_t)f * KDIM + q * 4);
        }
        // ---- fill: weights gather + values (4B each) ----
        for (int r0 = lane; r0 < n; r0 += 32) {
            const int f = load_idx<IS64>(feats, base + r0);
            cp4(w_s + (unsigned)r0 * 4u, weights + f);
            cp4(v_s + (unsigned)r0 * 4u, values + base + r0);
        }
        cp_commit();
        cp_wait0();
        __syncwarp();

        // ---- consume: lane l reads bytes [t*512 + l*16) -- conflict-free --
        const int iters = (n + 7) >> 3;
        for (int t = 0; t < iters; t++) {
            const int r  = 8 * t + g;
            const int rc = (r < n) ? r : (n - 1);
            const float vv = (r < n) ? buf->v[rc] : 0.f;
            const float4 e4 = buf->emb[rc * 4 + m];
            const float e0 = e4.x * vv, e1 = e4.y * vv,
                        e2 = e4.z * vv, e3 = e4.w * vv;
            t1.x += e0; t1.y += e1; t1.z += e2; t1.w += e3;
            t2   += e0 * e0 + e1 * e1 + e2 * e2 + e3 * e3;
            if (m == 0) first += buf->w[rc] * vv;
        }
        __syncwarp();   // reads done before next super-chunk overwrites
    }

    // reduce t1 over the 8 octet-groups (lane bits 2..4)
#pragma unroll
    for (int o = 4; o <= 16; o <<= 1) {
        t1.x += __shfl_xor_sync(0xffffffffu, t1.x, o);
        t1.y += __shfl_xor_sync(0xffffffffu, t1.y, o);
        t1.z += __shfl_xor_sync(0xffffffffu, t1.z, o);
        t1.w += __shfl_xor_sync(0xffffffffu, t1.w, o);
    }

    // |t1|^2 replicated 8x across g-groups -> coefficient 0.5/8 = 0.0625
    float r = 0.0625f * (t1.x * t1.x + t1.y * t1.y + t1.z * t1.z + t1.w * t1.w)
            - 0.5f * t2 + first;
    return warp_sum(r);
}

__global__ void __launch_bounds__(256)
fm_kernel(const void* __restrict__ feats,
          const float* __restrict__ values,
          const float* __restrict__ weights,
          const float* __restrict__ embedding,
          const float* __restrict__ bias,
          float* __restrict__ out) {
    __shared__ WarpBuf sbuf[8];

    const int warp = (blockIdx.x * blockDim.x + threadIdx.x) >> 5;
    const int lane = threadIdx.x & 31;
    if (warp >= BATCH) return;
    const int b = warp;
    WarpBuf* buf = &sbuf[(threadIdx.x >> 5)];

    const int s = g_row_ptr[b];
    const int e = g_row_ptr[b + 1];

    float r = 0.f;
    if (e > s) {
        if (g_is64) r = fm_row<true >(s, e, lane, buf, feats, values, weights, embedding);
        else        r = fm_row<false>(s, e, lane, buf, feats, values, weights, embedding);
    }

    if (lane == 0) {
        const float x = r + __ldg(bias);
        out[b] = 1.0f / (1.0f + expf(-x));
    }
}

// ---------------------------------------------------------------------------
extern "C" void kernel_launch(void* const* d_in, const int* in_sizes, int n_in,
                              void* d_out, int out_size) {
    const void*  index_p   = nullptr;
    const void*  feats_p   = nullptr;
    const float* values_p  = nullptr;
    const float* bias_p    = nullptr;
    const float* weights_p = nullptr;
    const float* embed_p   = nullptr;

    int triple = 0;
    for (int i = 0; i < n_in; i++) {
        int sz = in_sizes[i];
        if (sz == NNZ) {
            if      (triple == 0) index_p  = d_in[i];
            else if (triple == 1) feats_p  = d_in[i];
            else                  values_p = (const float*)d_in[i];
            triple++;
        } else if (sz == VOCAB) {
            weights_p = (const float*)d_in[i];
        } else if (sz == VOCAB * KDIM) {
            embed_p = (const float*)d_in[i];
        } else if (sz == 1) {
            bias_p = (const float*)d_in[i];   // last size-1 input is bias
        }
    }

    float* out = (float*)d_out;
    (void)out_size;

    rowptr_kernel<<<(NNZ + 255) / 256, 256>>>(index_p);
    fm_kernel<<<(BATCH * 32 + 255) / 256, 256>>>(feats_p, values_p, weights_p,
                                                 embed_p, bias_p, out);
}